// round 2
// baseline (speedup 1.0000x reference)
#include <cuda_runtime.h>
#include <cuda_bf16.h>

#define NN 50000
#define NE 800000
#define ET (NE + NN)      // edges + self loops
#define IC 128            // in channels
#define OC 128            // heads * out_ch
#define HEADS 4
#define CPH 32            // channels per head

// -------- scratch (static device globals; allowed) --------
__device__ float g_h[NN * OC];        // projected features
__device__ float g_asrc[NN * HEADS];  // att · h (src half)
__device__ float g_adst[NN * HEADS];  // att · h (dst half)
__device__ int   g_deg[NN];
__device__ int   g_off[NN + 1];
__device__ int   g_cur[NN];
__device__ int   g_csrc[ET];          // src node per CSR slot (sorted by dst)
__device__ int   g_is64;              // edge_index dtype flag (1 = int64)

// ============================================================
// dtype detection: int64 little-endian node ids (< 2^31) have
// all-zero high words; int32 node ids at odd positions are
// random in [0, 50000) -> essentially never 128 zeros in a row.
// ============================================================
__global__ void detect_kernel(const int* __restrict__ ei32) {
    if (threadIdx.x == 0 && blockIdx.x == 0) {
        int odd_nonzero = 0;
        for (int k = 0; k < 128; k++)
            if (ei32[2 * k + 1] != 0) odd_nonzero = 1;
        g_is64 = odd_nonzero ? 0 : 1;
    }
}

__device__ __forceinline__ int load_idx(const void* ei, int pos) {
    int v;
    if (g_is64) v = (int)((const long long*)ei)[pos];
    else        v = ((const int*)ei)[pos];
    // clamp: wrong-but-safe beats illegal access
    v = (v < 0) ? 0 : (v >= NN ? NN - 1 : v);
    return v;
}

// ============================================================
// Kernel 1: h = x @ W^T  (+ epilogue: a_src, a_dst per node)
// block = 256 thr (8 warps), tile = 128 rows x 128 cols, K=128
// ============================================================
__global__ __launch_bounds__(256) void gemm_kernel(
    const float* __restrict__ x, const float* __restrict__ W,
    const float* __restrict__ att)
{
    __shared__ float wt[64 * 132];   // [k_local][c] padded stride 132
    const int tid  = threadIdx.x;
    const int lane = tid & 31;
    const int wrp  = tid >> 5;
    const int row0 = blockIdx.x * 128 + wrp * 16;

    float acc[16][4];
#pragma unroll
    for (int r = 0; r < 16; r++)
#pragma unroll
        for (int j = 0; j < 4; j++) acc[r][j] = 0.f;

    const float4* x4 = (const float4*)x;
    const float4* W4 = (const float4*)W;

    for (int kh = 0; kh < 2; kh++) {
        __syncthreads();
        // load + transpose half of W: W[c][kh*64 + k] -> wt[k][c]
        for (int i = tid; i < 128 * 16; i += 256) {
            int c  = i >> 4;
            int k4 = i & 15;
            float4 v = W4[c * 32 + kh * 16 + k4];
            wt[(4 * k4 + 0) * 132 + c] = v.x;
            wt[(4 * k4 + 1) * 132 + c] = v.y;
            wt[(4 * k4 + 2) * 132 + c] = v.z;
            wt[(4 * k4 + 3) * 132 + c] = v.w;
        }
        __syncthreads();

#pragma unroll
        for (int kc = 0; kc < 8; kc++) {       // 8 k per chunk
            float4 wr[8];
#pragma unroll
            for (int kk = 0; kk < 8; kk++)
                wr[kk] = *(const float4*)&wt[(kc * 8 + kk) * 132 + lane * 4];
#pragma unroll
            for (int r = 0; r < 16; r++) {
                int row = row0 + r;
                if (row < NN) {
                    float4 xv0 = x4[row * 32 + kh * 16 + kc * 2 + 0];
                    float4 xv1 = x4[row * 32 + kh * 16 + kc * 2 + 1];
                    float xk[8] = {xv0.x, xv0.y, xv0.z, xv0.w,
                                   xv1.x, xv1.y, xv1.z, xv1.w};
#pragma unroll
                    for (int kk = 0; kk < 8; kk++) {
                        acc[r][0] += xk[kk] * wr[kk].x;
                        acc[r][1] += xk[kk] * wr[kk].y;
                        acc[r][2] += xk[kk] * wr[kk].z;
                        acc[r][3] += xk[kk] * wr[kk].w;
                    }
                }
            }
        }
    }

    // epilogue: store h, compute a_src/a_dst via 8-lane segmented reduce
    const int head = lane >> 3;
    const int cl   = (lane & 7) * 4;       // channel within head
    float as[4], ad[4];
#pragma unroll
    for (int j = 0; j < 4; j++) {
        as[j] = att[head * 64 + cl + j];
        ad[j] = att[head * 64 + 32 + cl + j];
    }
    float4* h4 = (float4*)g_h;
#pragma unroll
    for (int r = 0; r < 16; r++) {
        int row = row0 + r;
        if (row >= NN) continue;
        float4 hv;
        hv.x = acc[r][0]; hv.y = acc[r][1]; hv.z = acc[r][2]; hv.w = acc[r][3];
        h4[row * 32 + lane] = hv;
        float ps = acc[r][0] * as[0] + acc[r][1] * as[1] +
                   acc[r][2] * as[2] + acc[r][3] * as[3];
        float pd = acc[r][0] * ad[0] + acc[r][1] * ad[1] +
                   acc[r][2] * ad[2] + acc[r][3] * ad[3];
#pragma unroll
        for (int o = 4; o >= 1; o >>= 1) {
            ps += __shfl_xor_sync(0xffffffffu, ps, o);
            pd += __shfl_xor_sync(0xffffffffu, pd, o);
        }
        if ((lane & 7) == 0) {
            g_asrc[row * HEADS + head] = ps;
            g_adst[row * HEADS + head] = pd;
        }
    }
}

// ============================================================
// CSR build
// ============================================================
__global__ void zero_kernel() {
    int i = blockIdx.x * blockDim.x + threadIdx.x;
    if (i < NN) g_deg[i] = 0;
}

__global__ void hist_kernel(const void* __restrict__ ei) {
    int i = blockIdx.x * blockDim.x + threadIdx.x;
    if (i >= ET) return;
    int dst = (i < NE) ? load_idx(ei, NE + i) : (i - NE);
    atomicAdd(&g_deg[dst], 1);
}

__global__ void scan_kernel() {   // 1 block, 1024 threads
    __shared__ int sh[1024];
    __shared__ int carry;
    int tid = threadIdx.x;
    if (tid == 0) carry = 0;
    __syncthreads();
    const int CHUNKS = (NN + 1023) / 1024;
    for (int c = 0; c < CHUNKS; c++) {
        int i = c * 1024 + tid;
        int v = (i < NN) ? g_deg[i] : 0;
        sh[tid] = v;
        __syncthreads();
        for (int o = 1; o < 1024; o <<= 1) {
            int t = (tid >= o) ? sh[tid - o] : 0;
            __syncthreads();
            sh[tid] += t;
            __syncthreads();
        }
        int excl = carry + sh[tid] - v;
        if (i < NN) { g_off[i] = excl; g_cur[i] = excl; }
        int total = sh[1023];
        __syncthreads();
        if (tid == 0) carry += total;
        __syncthreads();
    }
    if (tid == 0) g_off[NN] = carry;
}

__global__ void scatter_kernel(const void* __restrict__ ei) {
    int i = blockIdx.x * blockDim.x + threadIdx.x;
    if (i >= ET) return;
    int src, dst;
    if (i < NE) { src = load_idx(ei, i); dst = load_idx(ei, NE + i); }
    else        { src = dst = i - NE; }
    int p = atomicAdd(&g_cur[dst], 1);
    if (p >= 0 && p < ET) g_csrc[p] = src;
}

// ============================================================
// Kernel 3: per-dst-node online-softmax aggregation
// 1 warp per node; lane owns 4 channels (head = lane>>3)
// ============================================================
__global__ __launch_bounds__(256) void gat_kernel(
    const float* __restrict__ bias, float* __restrict__ out)
{
    int gw   = (blockIdx.x * blockDim.x + threadIdx.x) >> 5;
    int lane = threadIdx.x & 31;
    if (gw >= NN) return;
    const int head = lane >> 3;

    const float adh = g_adst[gw * HEADS + head];
    const int beg = g_off[gw];
    const int end = g_off[gw + 1];

    float m = -1e30f, s = 0.f;
    float a0 = 0.f, a1 = 0.f, a2 = 0.f, a3 = 0.f;
    const float4* h4 = (const float4*)g_h;

    for (int i = beg; i < end; i++) {
        int src = g_csrc[i];
        float e = g_asrc[src * HEADS + head] + adh;
        e = (e > 0.f) ? e : 0.2f * e;          // leaky relu, slope 0.2
        float4 hv = h4[src * 32 + lane];
        float mn = fmaxf(m, e);
        float sc = __expf(m - mn);             // 1 if no new max; 0 on first iter
        float p  = __expf(e - mn);
        s  = s * sc + p;
        a0 = a0 * sc + p * hv.x;
        a1 = a1 * sc + p * hv.y;
        a2 = a2 * sc + p * hv.z;
        a3 = a3 * sc + p * hv.w;
        m = mn;
    }

    float inv = 1.f / fmaxf(s, 1e-10f);
    const float4* b4 = (const float4*)bias;
    float4 bv = b4[lane];
    float4 o;
    o.x = a0 * inv + bv.x;
    o.y = a1 * inv + bv.y;
    o.z = a2 * inv + bv.z;
    o.w = a3 * inv + bv.w;
    ((float4*)out)[gw * 32 + lane] = o;
}

// ============================================================
extern "C" void kernel_launch(void* const* d_in, const int* in_sizes, int n_in,
                              void* d_out, int out_size)
{
    const float* x    = (const float*)d_in[0];
    const void*  ei   = d_in[1];
    const float* W    = (const float*)d_in[2];
    const float* att  = (const float*)d_in[3];
    const float* bias = (const float*)d_in[4];
    float*       out  = (float*)d_out;

    detect_kernel<<<1, 32>>>((const int*)ei);
    gemm_kernel<<<(NN + 127) / 128, 256>>>(x, W, att);
    zero_kernel<<<(NN + 255) / 256, 256>>>();
    hist_kernel<<<(ET + 255) / 256, 256>>>(ei);
    scan_kernel<<<1, 1024>>>();
    scatter_kernel<<<(ET + 255) / 256, 256>>>(ei);
    gat_kernel<<<((long)NN * 32 + 255) / 256, 256>>>(bias, out);
}

// round 3
// speedup vs baseline: 1.3078x; 1.3078x over previous
#include <cuda_runtime.h>
#include <cuda_bf16.h>

#define NN 50000
#define NE 800000
#define ET (NE + NN)      // edges + self loops
#define IC 128
#define OC 128
#define HEADS 4
#define SCAN_BLK 13       // ceil(50000 / 4096)

// -------- scratch (static device globals; allowed) --------
__device__ float g_h[NN * OC];
__device__ float g_asrc[NN * HEADS];
__device__ float g_adst[NN * HEADS];
__device__ int   g_deg[NN];
__device__ int   g_off[NN + 1];
__device__ int   g_cur[NN];
__device__ int   g_csrc[ET];
__device__ int   g_bsum[SCAN_BLK];
__device__ int   g_is64;

// ============================================================
// zero degrees + detect edge_index dtype (block 0 thread 0)
// ============================================================
__global__ void zero_detect_kernel(const int* __restrict__ ei32) {
    int i = blockIdx.x * blockDim.x + threadIdx.x;
    if (i < NN) g_deg[i] = 0;
    if (i == 0) {
        int odd_nonzero = 0;
        for (int k = 0; k < 128; k++)
            if (ei32[2 * k + 1] != 0) odd_nonzero = 1;
        g_is64 = odd_nonzero ? 0 : 1;
    }
}

__device__ __forceinline__ int load_idx(const void* ei, int pos) {
    int v;
    if (g_is64) v = (int)((const long long*)ei)[pos];
    else        v = ((const int*)ei)[pos];
    v = (v < 0) ? 0 : (v >= NN ? NN - 1 : v);
    return v;
}

// ============================================================
// GEMM: h = x @ W^T (+ per-node att dot products) — side stream
// ============================================================
__global__ __launch_bounds__(256) void gemm_kernel(
    const float* __restrict__ x, const float* __restrict__ W,
    const float* __restrict__ att)
{
    __shared__ float wt[64 * 132];
    const int tid  = threadIdx.x;
    const int lane = tid & 31;
    const int wrp  = tid >> 5;
    const int row0 = blockIdx.x * 128 + wrp * 16;

    float acc[16][4];
#pragma unroll
    for (int r = 0; r < 16; r++)
#pragma unroll
        for (int j = 0; j < 4; j++) acc[r][j] = 0.f;

    const float4* x4 = (const float4*)x;
    const float4* W4 = (const float4*)W;

    for (int kh = 0; kh < 2; kh++) {
        __syncthreads();
        for (int i = tid; i < 128 * 16; i += 256) {
            int c  = i >> 4;
            int k4 = i & 15;
            float4 v = W4[c * 32 + kh * 16 + k4];
            wt[(4 * k4 + 0) * 132 + c] = v.x;
            wt[(4 * k4 + 1) * 132 + c] = v.y;
            wt[(4 * k4 + 2) * 132 + c] = v.z;
            wt[(4 * k4 + 3) * 132 + c] = v.w;
        }
        __syncthreads();

#pragma unroll
        for (int kc = 0; kc < 8; kc++) {
            float4 wr[8];
#pragma unroll
            for (int kk = 0; kk < 8; kk++)
                wr[kk] = *(const float4*)&wt[(kc * 8 + kk) * 132 + lane * 4];
#pragma unroll
            for (int r = 0; r < 16; r++) {
                int row = row0 + r;
                if (row < NN) {
                    float4 xv0 = x4[row * 32 + kh * 16 + kc * 2 + 0];
                    float4 xv1 = x4[row * 32 + kh * 16 + kc * 2 + 1];
                    float xk[8] = {xv0.x, xv0.y, xv0.z, xv0.w,
                                   xv1.x, xv1.y, xv1.z, xv1.w};
#pragma unroll
                    for (int kk = 0; kk < 8; kk++) {
                        acc[r][0] += xk[kk] * wr[kk].x;
                        acc[r][1] += xk[kk] * wr[kk].y;
                        acc[r][2] += xk[kk] * wr[kk].z;
                        acc[r][3] += xk[kk] * wr[kk].w;
                    }
                }
            }
        }
    }

    const int head = lane >> 3;
    const int cl   = (lane & 7) * 4;
    float as[4], ad[4];
#pragma unroll
    for (int j = 0; j < 4; j++) {
        as[j] = att[head * 64 + cl + j];
        ad[j] = att[head * 64 + 32 + cl + j];
    }
    float4* h4 = (float4*)g_h;
#pragma unroll
    for (int r = 0; r < 16; r++) {
        int row = row0 + r;
        if (row >= NN) continue;
        float4 hv;
        hv.x = acc[r][0]; hv.y = acc[r][1]; hv.z = acc[r][2]; hv.w = acc[r][3];
        h4[row * 32 + lane] = hv;
        float ps = acc[r][0] * as[0] + acc[r][1] * as[1] +
                   acc[r][2] * as[2] + acc[r][3] * as[3];
        float pd = acc[r][0] * ad[0] + acc[r][1] * ad[1] +
                   acc[r][2] * ad[2] + acc[r][3] * ad[3];
#pragma unroll
        for (int o = 4; o >= 1; o >>= 1) {
            ps += __shfl_xor_sync(0xffffffffu, ps, o);
            pd += __shfl_xor_sync(0xffffffffu, pd, o);
        }
        if ((lane & 7) == 0) {
            g_asrc[row * HEADS + head] = ps;
            g_adst[row * HEADS + head] = pd;
        }
    }
}

// ============================================================
// CSR build
// ============================================================
__global__ void hist_kernel(const void* __restrict__ ei) {
    int i = blockIdx.x * blockDim.x + threadIdx.x;
    if (i >= ET) return;
    int dst = (i < NE) ? load_idx(ei, NE + i) : (i - NE);
    atomicAdd(&g_deg[dst], 1);
}

// two-level scan: stage A — 13 blocks, each scans 4096 elems (4/thread)
__global__ __launch_bounds__(1024) void scan_a_kernel() {
    __shared__ int sh[1024];
    const int tid  = threadIdx.x;
    const int base = blockIdx.x * 4096 + tid * 4;
    int v[4];
#pragma unroll
    for (int j = 0; j < 4; j++)
        v[j] = (base + j < NN) ? g_deg[base + j] : 0;
    int t = v[0] + v[1] + v[2] + v[3];
    sh[tid] = t;
    __syncthreads();
    for (int o = 1; o < 1024; o <<= 1) {
        int u = (tid >= o) ? sh[tid - o] : 0;
        __syncthreads();
        sh[tid] += u;
        __syncthreads();
    }
    int p = sh[tid] - t;             // exclusive prefix of this thread
#pragma unroll
    for (int j = 0; j < 4; j++) {
        if (base + j < NN) g_off[base + j] = p;
        p += v[j];
    }
    if (tid == 1023) g_bsum[blockIdx.x] = sh[1023];
}

// stage B — add block prefixes (each block serially scans 13 sums)
__global__ __launch_bounds__(1024) void scan_b_kernel() {
    __shared__ int addv;
    const int tid  = threadIdx.x;
    const int base = blockIdx.x * 4096 + tid * 4;
    if (tid == 0) {
        int run = 0;
        for (int b = 0; b < (int)blockIdx.x; b++) run += g_bsum[b];
        addv = run;
    }
    __syncthreads();
    int add = addv;
#pragma unroll
    for (int j = 0; j < 4; j++) {
        int i = base + j;
        if (i < NN) {
            int o = g_off[i] + add;
            g_off[i] = o;
            g_cur[i] = o;
        }
    }
    if (blockIdx.x == 0 && tid == 0) g_off[NN] = ET;
}

__global__ void scatter_kernel(const void* __restrict__ ei) {
    int i = blockIdx.x * blockDim.x + threadIdx.x;
    if (i >= ET) return;
    int src, dst;
    if (i < NE) { src = load_idx(ei, i); dst = load_idx(ei, NE + i); }
    else        { src = dst = i - NE; }
    int p = atomicAdd(&g_cur[dst], 1);
    if (p >= 0 && p < ET) g_csrc[p] = src;
}

// ============================================================
// per-dst online-softmax aggregation: 1 warp per node
// ============================================================
__global__ __launch_bounds__(256) void gat_kernel(
    const float* __restrict__ bias, float* __restrict__ out)
{
    int gw   = (blockIdx.x * blockDim.x + threadIdx.x) >> 5;
    int lane = threadIdx.x & 31;
    if (gw >= NN) return;
    const int head = lane >> 3;

    const float adh = g_adst[gw * HEADS + head];
    const int beg = g_off[gw];
    const int end = g_off[gw + 1];

    float m = -1e30f, s = 0.f;
    float a0 = 0.f, a1 = 0.f, a2 = 0.f, a3 = 0.f;
    const float4* h4 = (const float4*)g_h;

    for (int i = beg; i < end; i++) {
        int src = g_csrc[i];
        float e = g_asrc[src * HEADS + head] + adh;
        e = (e > 0.f) ? e : 0.2f * e;
        float4 hv = h4[src * 32 + lane];
        float mn = fmaxf(m, e);
        float sc = __expf(m - mn);
        float p  = __expf(e - mn);
        s  = s * sc + p;
        a0 = a0 * sc + p * hv.x;
        a1 = a1 * sc + p * hv.y;
        a2 = a2 * sc + p * hv.z;
        a3 = a3 * sc + p * hv.w;
        m = mn;
    }

    float inv = 1.f / fmaxf(s, 1e-10f);
    const float4* b4 = (const float4*)bias;
    float4 bv = b4[lane];
    float4 o;
    o.x = a0 * inv + bv.x;
    o.y = a1 * inv + bv.y;
    o.z = a2 * inv + bv.z;
    o.w = a3 * inv + bv.w;
    ((float4*)out)[gw * 32 + lane] = o;
}

// ============================================================
extern "C" void kernel_launch(void* const* d_in, const int* in_sizes, int n_in,
                              void* d_out, int out_size)
{
    const float* x    = (const float*)d_in[0];
    const void*  ei   = d_in[1];
    const float* W    = (const float*)d_in[2];
    const float* att  = (const float*)d_in[3];
    const float* bias = (const float*)d_in[4];
    float*       out  = (float*)d_out;

    // one-time stream/event setup (first call = correctness run, not captured)
    static cudaStream_t s_side = nullptr;
    static cudaEvent_t  ev_fork = nullptr, ev_join = nullptr;
    if (!s_side) {
        cudaStreamCreateWithFlags(&s_side, cudaStreamNonBlocking);
        cudaEventCreateWithFlags(&ev_fork, cudaEventDisableTiming);
        cudaEventCreateWithFlags(&ev_join, cudaEventDisableTiming);
    }

    // fork: GEMM on side stream, CSR chain on main stream
    cudaEventRecord(ev_fork, 0);
    cudaStreamWaitEvent(s_side, ev_fork, 0);
    gemm_kernel<<<(NN + 127) / 128, 256, 0, s_side>>>(x, W, att);
    cudaEventRecord(ev_join, s_side);

    zero_detect_kernel<<<(NN + 255) / 256, 256>>>((const int*)ei);
    hist_kernel<<<(ET + 255) / 256, 256>>>(ei);
    scan_a_kernel<<<SCAN_BLK, 1024>>>();
    scan_b_kernel<<<SCAN_BLK, 1024>>>();
    scatter_kernel<<<(ET + 255) / 256, 256>>>(ei);

    // join, then aggregate
    cudaStreamWaitEvent(0, ev_join, 0);
    gat_kernel<<<((long)NN * 32 + 255) / 256, 256>>>(bias, out);
}